// round 1
// baseline (speedup 1.0000x reference)
#include <cuda_runtime.h>

#define ROWS   4096
#define NCOLS  16384
#define NPAIRS 8199            // outputs per filter per row
#define OUTROW (2 * NPAIRS)    // 16398
#define BLOCK  256
#define PAIRS_PER_BLOCK 2048
#define BLOCKS_X 4             // 4*2048 = 8192; last block also takes the 7-pair tail
#define MAX_PAIRS_LAST (NPAIRS - 3 * PAIRS_PER_BLOCK)   // 2055
#define SMEM_FLOATS 4120       // 2*2055 + 8 = 4118, padded to /4
#define SMEM_VEC (SMEM_FLOATS / 4)  // 1030 float4 slots

// Filter taps in window order: w[j] = x[2m-6+j] pairs with DEC[7-j]
__device__ __constant__ const float CA_W[8] = {
     0.23037781330885523f,  0.7148465705525415f,   0.6308807679295904f,
    -0.02798376941698385f, -0.18703481171888114f,  0.030841381835986965f,
     0.032883011666982945f, -0.010597401784997278f };
__device__ __constant__ const float CD_W[8] = {
    -0.010597401784997278f, -0.032883011666982945f, 0.030841381835986965f,
     0.18703481171888114f,  -0.02798376941698385f, -0.6308807679295904f,
     0.7148465705525415f,   -0.23037781330885523f };

__global__ __launch_bounds__(BLOCK)
void dwt_db4_kernel(const float* __restrict__ x, float* __restrict__ out)
{
    __shared__ float s[SMEM_FLOATS];

    const int row  = blockIdx.y;
    const int m0   = blockIdx.x * PAIRS_PER_BLOCK;
    const int base = 2 * m0 - 8;                    // x column of s[0]; %4 == 0
    const long long rbase = (long long)row * NCOLS;
    const float* xr = x + rbase;

    // ---- stage input tile into smem (each global float loaded exactly once) ----
    for (int j = threadIdx.x; j < SMEM_VEC; j += BLOCK) {
        const int gi = base + 4 * j;
        float4 v;
        if (gi >= 0 && gi + 3 < NCOLS) {
            v = *reinterpret_cast<const float4*>(xr + gi);
        } else {
            v.x = (gi + 0 >= 0 && gi + 0 < NCOLS) ? xr[gi + 0] : 0.0f;
            v.y = (gi + 1 >= 0 && gi + 1 < NCOLS) ? xr[gi + 1] : 0.0f;
            v.z = (gi + 2 >= 0 && gi + 2 < NCOLS) ? xr[gi + 2] : 0.0f;
            v.w = (gi + 3 >= 0 && gi + 3 < NCOLS) ? xr[gi + 3] : 0.0f;
        }
        *reinterpret_cast<float4*>(s + 4 * j) = v;
    }
    __syncthreads();

    const int np = (blockIdx.x == BLOCKS_X - 1) ? (NPAIRS - m0) : PAIRS_PER_BLOCK;
    float* __restrict__ orow = out + (long long)row * OUTROW;

    // 9 strided iterations: covers up to 2304 >= 2055 pairs
    #pragma unroll
    for (int i = 0; i < 9; i++) {
        const int l = threadIdx.x + i * BLOCK;      // local pair index
        if (l < np) {
            const int m = m0 + l;
            const float* __restrict__ w = s + 2 * l + 2;  // = x[2m-6 ...]
            // float2-aligned (2l+2 even) -> LDS.64, conflict-free at 8B/lane stride
            float2 p0 = *reinterpret_cast<const float2*>(w + 0);
            float2 p1 = *reinterpret_cast<const float2*>(w + 2);
            float2 p2 = *reinterpret_cast<const float2*>(w + 4);
            float2 p3 = *reinterpret_cast<const float2*>(w + 6);
            const float wv[8] = { p0.x, p0.y, p1.x, p1.y, p2.x, p2.y, p3.x, p3.y };

            float a = 0.0f, d = 0.0f;
            #pragma unroll
            for (int j = 0; j < 8; j++) {
                a = fmaf(CA_W[j], wv[j], a);
                d = fmaf(CD_W[j], wv[j], d);
            }
            orow[m]          = a;   // cA, coalesced across warp
            orow[NPAIRS + m] = d;   // cD, coalesced across warp
        }
    }
}

extern "C" void kernel_launch(void* const* d_in, const int* in_sizes, int n_in,
                              void* d_out, int out_size)
{
    const float* x = (const float*)d_in[0];
    float* out = (float*)d_out;
    dim3 grid(BLOCKS_X, ROWS);
    dwt_db4_kernel<<<grid, BLOCK>>>(x, out);
}

// round 3
// speedup vs baseline: 1.1201x; 1.1201x over previous
#include <cuda_runtime.h>

#define ROWS   4096
#define NCOLS  16384
#define NPAIRS 8199
#define OUTROW 16398
#define BLOCK  256
#define GROUPS_TOTAL     4100   // group g -> cA(2g),cA(2g+1), cD(2g-1),cD(2g)
#define BLOCKS_X         5
#define GROUPS_PER_BLOCK 820    // 5*820 = 4100 exactly
#define SMEM_FLOATS      3288   // x[4g0-8 .. 4g0+3279]
#define SMEM_VEC         822    // float4 slots

// Window order: pair m reads x[2m-6+j], tap j pairs with DEC[7-j]
__device__ constexpr float CA_W[8] = {
     0.23037781330885523f,  0.7148465705525415f,   0.6308807679295904f,
    -0.02798376941698385f, -0.18703481171888114f,  0.030841381835986965f,
     0.032883011666982945f, -0.010597401784997278f };
__device__ constexpr float CD_W[8] = {
    -0.010597401784997278f, -0.032883011666982945f, 0.030841381835986965f,
     0.18703481171888114f,  -0.02798376941698385f, -0.6308807679295904f,
     0.7148465705525415f,   -0.23037781330885523f };

__global__ __launch_bounds__(BLOCK)
void dwt_db4_kernel(const float* __restrict__ x, float* __restrict__ out)
{
    __shared__ float s[SMEM_FLOATS];

    const int row  = blockIdx.y;
    const int g0   = blockIdx.x * GROUPS_PER_BLOCK;
    const int base = 4 * g0 - 8;                 // x index of s[0]; %4 == 0
    const float* __restrict__ xr = x + (size_t)row * NCOLS;

    // ---- stage tile: each global float touched exactly once, L1 bypassed ----
    if (blockIdx.x != 0 && blockIdx.x != BLOCKS_X - 1) {
        #pragma unroll
        for (int i = 0; i < 4; i++) {
            const int j = threadIdx.x + i * BLOCK;
            if (j < SMEM_VEC) {
                float4 v = __ldcg(reinterpret_cast<const float4*>(xr + base + 4 * j));
                *reinterpret_cast<float4*>(s + 4 * j) = v;
            }
        }
    } else {
        #pragma unroll
        for (int i = 0; i < 4; i++) {
            const int j = threadIdx.x + i * BLOCK;
            if (j < SMEM_VEC) {
                const int gi = base + 4 * j;
                float4 v;
                if (gi >= 0 && gi + 3 < NCOLS) {
                    v = __ldcg(reinterpret_cast<const float4*>(xr + gi));
                } else {
                    v.x = (gi + 0 >= 0 && gi + 0 < NCOLS) ? xr[gi + 0] : 0.0f;
                    v.y = (gi + 1 >= 0 && gi + 1 < NCOLS) ? xr[gi + 1] : 0.0f;
                    v.z = (gi + 2 >= 0 && gi + 2 < NCOLS) ? xr[gi + 2] : 0.0f;
                    v.w = (gi + 3 >= 0 && gi + 3 < NCOLS) ? xr[gi + 3] : 0.0f;
                }
                *reinterpret_cast<float4*>(s + 4 * j) = v;
            }
        }
    }
    __syncthreads();

    float* __restrict__ orow = out + (size_t)row * OUTROW;

    #pragma unroll
    for (int i = 0; i < 4; i++) {
        const int gl = threadIdx.x + i * BLOCK;        // local group
        if (gl < GROUPS_PER_BLOCK) {
            const int g = g0 + gl;
            // 12-float window x[4g-8 .. 4g+3] via 3 conflict-free LDS.128
            const float* wp = s + 4 * gl;
            const float4 v0 = *reinterpret_cast<const float4*>(wp + 0);
            const float4 v1 = *reinterpret_cast<const float4*>(wp + 4);
            const float4 v2 = *reinterpret_cast<const float4*>(wp + 8);
            const float wv[12] = { v0.x, v0.y, v0.z, v0.w,
                                   v1.x, v1.y, v1.z, v1.w,
                                   v2.x, v2.y, v2.z, v2.w };

            float a0 = 0.f, a1 = 0.f, dm = 0.f, d0 = 0.f;
            #pragma unroll
            for (int j = 0; j < 8; j++) {
                a0 = fmaf(CA_W[j], wv[j + 2], a0);   // cA(2g)
                a1 = fmaf(CA_W[j], wv[j + 4], a1);   // cA(2g+1)
                dm = fmaf(CD_W[j], wv[j + 0], dm);   // cD(2g-1)
                d0 = fmaf(CD_W[j], wv[j + 2], d0);   // cD(2g)
            }

            // cA: pairs {2g, 2g+1} -> float2 at orow[2g] (8B aligned)
            if (g < GROUPS_TOTAL - 1) {
                __stcs(reinterpret_cast<float2*>(orow + 2 * g),
                       make_float2(a0, a1));
            } else {                                  // g=4099: only pair 8198 exists
                __stcs(orow + 2 * g, a0);
            }
            // cD: pairs {2g-1, 2g} -> float2 at orow[8198 + 2g] (8B aligned)
            if (g > 0) {
                __stcs(reinterpret_cast<float2*>(orow + (NPAIRS - 1) + 2 * g),
                       make_float2(dm, d0));
            } else {                                  // g=0: only cD(0)
                __stcs(orow + NPAIRS, d0);
            }
        }
    }
}

extern "C" void kernel_launch(void* const* d_in, const int* in_sizes, int n_in,
                              void* d_out, int out_size)
{
    const float* x = (const float*)d_in[0];
    float* out = (float*)d_out;
    dim3 grid(BLOCKS_X, ROWS);
    dwt_db4_kernel<<<grid, BLOCK>>>(x, out);
}